// round 15
// baseline (speedup 1.0000x reference)
#include <cuda_runtime.h>
#include <cuda_bf16.h>
#include <math.h>
#include <stdint.h>
#include <stddef.h>

// fixed problem shapes
#define BDIM 8
#define HDIM 8
#define DM 512
#define DA 256
#define DP 128
#define MDIM 32
#define DK 64
#define DAH 32
#define DPH 16
#define SDIM 6144

// ---------------- device scratch ----------------
__device__ __nv_bfloat16 d_Xbf[(size_t)BDIM*SDIM*DM];
__device__ __nv_bfloat16 d_Abf[(size_t)BDIM*SDIM*DA];
__device__ __nv_bfloat16 d_Pbf[(size_t)BDIM*SDIM*DP];
__device__ __nv_bfloat16 d_WkMbf[HDIM*DK*DM];
__device__ __nv_bfloat16 d_Wkabf[HDIM*DAH*DA];
__device__ __nv_bfloat16 d_Wkpbf[HDIM*DPH*DP];
__device__ float d_WqMT[HDIM*DM*DK];
__device__ float d_WvMT[HDIM*DM*DK];
__device__ float d_WOMT[DM*DM];
__device__ float d_WihT[DM*192];
__device__ float d_WhhT[DK*192];
__device__ __nv_bfloat16 d_Knbf[(size_t)BDIM*HDIM*SDIM*DK];
__device__ __nv_bfloat16 d_Qvbf[BDIM*HDIM*MDIM*DK];
__device__ float d_QA[BDIM*HDIM*DAH];
__device__ float d_QP[BDIM*HDIM*DPH];
__device__ float d_tn[BDIM*HDIM*SDIM];
__device__ float d_dot2[BDIM*HDIM*SDIM];
__device__ float d_dot3[BDIM*HDIM*SDIM];
__device__ float d_attn[BDIM*HDIM*SDIM];
__device__ float d_alast[BDIM*HDIM];
__device__ float d_xbar[BDIM*HDIM*DM];
__device__ float d_gi[BDIM*31*192];
__device__ float d_res[BDIM*DK];

__device__ __forceinline__ void mma_bf16(float* c, const uint32_t* a, uint32_t b0, uint32_t b1) {
    asm volatile("mma.sync.aligned.m16n8k16.row.col.f32.bf16.bf16.f32 "
        "{%0,%1,%2,%3}, {%4,%5,%6,%7}, {%8,%9}, {%0,%1,%2,%3};\n"
        : "+f"(c[0]), "+f"(c[1]), "+f"(c[2]), "+f"(c[3])
        : "r"(a[0]), "r"(a[1]), "r"(a[2]), "r"(a[3]), "r"(b0), "r"(b1));
}

__device__ __forceinline__ void ldsm_x4(uint32_t* r, uint32_t addr) {
    asm volatile("ldmatrix.sync.aligned.m8n8.x4.shared.b16 {%0,%1,%2,%3}, [%4];"
        : "=r"(r[0]), "=r"(r[1]), "=r"(r[2]), "=r"(r[3]) : "r"(addr));
}
__device__ __forceinline__ void ldsm_x2(uint32_t* r, uint32_t addr) {
    asm volatile("ldmatrix.sync.aligned.m8n8.x2.shared.b16 {%0,%1}, [%2];"
        : "=r"(r[0]), "=r"(r[1]) : "r"(addr));
}

__device__ __forceinline__ void cpa16(uint32_t saddr, const void* g) {
    asm volatile("cp.async.cg.shared.global [%0], [%1], 16;" :: "r"(saddr), "l"(g));
}
__device__ __forceinline__ void cpa_commit() { asm volatile("cp.async.commit_group;"); }
__device__ __forceinline__ void cpa_wait0() { asm volatile("cp.async.wait_group 0;" ::: "memory"); }

__device__ __forceinline__ uint32_t packbf(float a, float b) {
    __nv_bfloat162 t = __floats2bfloat162_rn(a, b);
    return *(uint32_t*)&t;
}

// ---------------- fp32 -> bf16 conversion (2D grid, shift indexing) ----------------
__global__ void __launch_bounds__(256) convert_kernel(
        const float* __restrict__ memory, const float* __restrict__ x_pre,
        const float* __restrict__ aux, const float* __restrict__ pos, int S) {
    int b = blockIdx.y;
    int stride = gridDim.x*256;
    int t0 = blockIdx.x*256 + threadIdx.x;
    int nX = S << 7;
    const float* memB = memory + (size_t)b*(S-1)*DM;
    __nv_bfloat16* XB = d_Xbf + (size_t)b*S*DM;
    for (int j = t0; j < nX; j += stride) {
        int s = j >> 7, d4 = (j & 127) << 2;
        const float* src = (s < S-1) ? memB + ((size_t)s << 9) + d4 : x_pre + ((size_t)b << 9) + d4;
        float4 v = *(const float4*)src;
        uint2 o; o.x = packbf(v.x, v.y); o.y = packbf(v.z, v.w);
        *(uint2*)&XB[((size_t)s << 9) + d4] = o;
    }
    int nA = S << 6;
    const float* auxB = aux + (size_t)b*S*DA;
    __nv_bfloat16* AB = d_Abf + (size_t)b*S*DA;
    for (int j = t0; j < nA; j += stride) {
        float4 v = *(const float4*)(auxB + ((size_t)j << 2));
        uint2 o; o.x = packbf(v.x, v.y); o.y = packbf(v.z, v.w);
        *(uint2*)&AB[(size_t)j << 2] = o;
    }
    int nP = S << 5;
    const float* posB = pos + (size_t)b*S*DP;
    __nv_bfloat16* PB = d_Pbf + (size_t)b*S*DP;
    for (int j = t0; j < nP; j += stride) {
        float4 v = *(const float4*)(posB + ((size_t)j << 2));
        uint2 o; o.x = packbf(v.x, v.y); o.y = packbf(v.z, v.w);
        *(uint2*)&PB[(size_t)j << 2] = o;
    }
}

// ---------------- masked weights (+ transposes, bf16 copies) + zero xbar ----------------
__global__ void mask_kernel(const float* __restrict__ Wq, const float* __restrict__ Wk,
                            const float* __restrict__ Wv, const float* __restrict__ WO,
                            const float* __restrict__ W_ih, const float* __restrict__ W_hh,
                            const float* __restrict__ Wka, const float* __restrict__ Wkp,
                            const int* __restrict__ G) {
    int i = blockIdx.x*256 + threadIdx.x;
    const int NW = HDIM*DK*DM;
    if (i < NW) {
        int h = i >> 15;
        int c = (i >> 9) & 63;
        int d = i & 511;
        float g = (float)G[c*64 + (d & 63)];
        d_WkMbf[i] = __float2bfloat16(Wk[i]*g);
        d_WqMT[((size_t)h*DM + d)*DK + c] = Wq[i]*g;
        d_WvMT[((size_t)h*DM + d)*DK + c] = Wv[i]*g;
    }
    if (i < HDIM*DAH*DA) d_Wkabf[i] = __float2bfloat16(Wka[i]);
    if (i < HDIM*DPH*DP) d_Wkpbf[i] = __float2bfloat16(Wkp[i]);
    if (i < DM*DM) {
        int j = i & 511, r = i >> 9;
        d_WOMT[(size_t)j*DM + r] = WO[i]*(float)G[(r & 63)*64 + (j & 63)];
    }
    if (i < 192*DM) {
        int j = i >> 9, d = i & 511;
        d_WihT[d*192 + j] = W_ih[i];
    }
    if (i < 192*DK) {
        int j = i >> 6, k = i & 63;
        d_WhhT[k*192 + j] = W_hh[i];
    }
    if (i < BDIM*HDIM*DM) d_xbar[i] = 0.f;
}

// ---------------- Qv: last M rows (4 rows per block), masked proj + l2norm ----------------
__global__ void __launch_bounds__(256) qv_kernel(const float* __restrict__ memory,
                          const float* __restrict__ x_pre,
                          const float* __restrict__ bq, int S) {
    int mgrp = blockIdx.x & 7, h = (blockIdx.x >> 3) & 7, b = blockIdx.x >> 6;
    __shared__ float xs[4][DM];
    __shared__ float wp[4][2];
    int tid = threadIdx.x;
    int mg = tid >> 6, c = tid & 63;
    for (int i = tid; i < 4*DM; i += 256) {
        int r = i >> 9, d = i & 511;
        int s = S - MDIM + mgrp*4 + r;
        const float* row = (s < S-1) ? memory + ((size_t)b*(S-1) + s)*DM : x_pre + (size_t)b*DM;
        xs[r][d] = row[d];
    }
    __syncthreads();
    const float* wt = d_WqMT + (size_t)h*DM*DK;
    float acc = bq[h*DK + c];
    #pragma unroll 8
    for (int d = 0; d < DM; d++) acc += xs[mg][d]*wt[d*DK + c];
    float v = acc*acc;
    for (int o = 16; o; o >>= 1) v += __shfl_xor_sync(0xffffffffu, v, o);
    if ((tid & 31) == 0) wp[mg][(c >> 5)] = v;
    __syncthreads();
    float inv = 1.f / fmaxf(sqrtf(wp[mg][0] + wp[mg][1]), 1e-12f);
    int m = mgrp*4 + mg;
    d_Qvbf[(((size_t)b*HDIM + h)*MDIM + m)*DK + c] = __float2bfloat16(acc*inv);
}

// ---------------- tensor-core projection ----------------
// HPW = heads per warp. Heads per block = 2*HPW.
// MODE 0: kproj  (HPW=1, DOUT=128) -> d_Knbf
// MODE 1: aux    (HPW=2, DOUT=128, 4 heads) -> dot QA -> d_dot2
// MODE 2: pos    (HPW=2, DOUT=64,  4 heads) -> dot QP -> d_dot3
template<int DIN, int DOUT, int MODE, int HPW>
__global__ void __launch_bounds__(256)
proj_mma_kernel(const __nv_bfloat16* __restrict__ src, const __nv_bfloat16* __restrict__ W,
                const float* __restrict__ bias, int S, int Wn) {
    constexpr int NW_N = 2;
    constexpr int TM   = 128;
    constexpr int WT_N = DOUT/NW_N;      // cols per warp
    constexpr int NFN  = WT_N/8;
    constexpr int NH   = NFN/HPW;        // fragments per head
    constexpr int HPB  = 2*HPW;          // heads per block
    constexpr int KC   = 128;
    constexpr int NCH  = DIN/KC;
    constexpr int RS   = 68;

    extern __shared__ uint32_t dynsm[];
    uint32_t* Xs  = dynsm;
    uint32_t* Wss = dynsm + TM*RS;
    __shared__ float bs_s[DOUT];
    __shared__ float qs_s[DOUT];

    int tid = threadIdx.x;
    int lane = tid & 31, wid = tid >> 5;
    int g = lane >> 2, tig = lane & 3;
    int warp_n = wid % NW_N, warp_m = wid / NW_N;
    int rb = warp_m*32, cb = warp_n*WT_N;
    int s0 = blockIdx.x*TM, hb = blockIdx.y, b = blockIdx.z;

    uint32_t xB = (uint32_t)__cvta_generic_to_shared(Xs);
    uint32_t wB = (uint32_t)__cvta_generic_to_shared(Wss);

    uint32_t aAddr[2];
    #pragma unroll
    for (int mi = 0; mi < 2; mi++)
        aAddr[mi] = xB + ((rb + mi*16 + (lane & 7) + (lane & 8))*RS + ((lane >> 4) & 1)*4)*4;
    uint32_t bAddr[(NFN + 1)/2];
    #pragma unroll
    for (int pg = 0; pg < (NFN + 1)/2; pg++) {
        if (NFN == 1)
            bAddr[pg] = wB + ((cb + (lane & 7))*RS + ((lane >> 3) & 1)*4)*4;
        else
            bAddr[pg] = wB + ((cb + pg*16 + ((lane >> 4) & 1)*8 + (lane & 7))*RS + ((lane >> 3) & 1)*4)*4;
    }

    for (int i = tid; i < DOUT; i += 256) {
        bs_s[i] = bias[hb*DOUT + i];
        if (MODE == 1) qs_s[i] = d_QA[(size_t)(b*HDIM + hb*HPB + (i >> 5))*DAH + (i & 31)];
        if (MODE == 2) qs_s[i] = d_QP[(size_t)(b*HDIM + hb*HPB + (i >> 4))*DPH + (i & 15)];
    }

    float acc[2][NFN][4];
    #pragma unroll
    for (int mi = 0; mi < 2; mi++)
        #pragma unroll
        for (int ni = 0; ni < NFN; ni++)
            #pragma unroll
            for (int q = 0; q < 4; q++) acc[mi][ni][q] = 0.f;

    for (int ch = 0; ch < NCH; ch++) {
        int d0 = ch*KC;
        #pragma unroll
        for (int it = 0; it < TM*16/256; it++) {
            int e = it*256 + tid;
            int row = e >> 4, seg = e & 15;
            cpa16(xB + (row*RS + seg*4)*4, src + ((size_t)b*S + s0 + row)*DIN + d0 + seg*8);
        }
        for (int e = tid; e < DOUT*16; e += 256) {
            int rr = e >> 4, seg = e & 15;
            cpa16(wB + (rr*RS + seg*4)*4, W + ((size_t)(hb*DOUT + rr))*DIN + d0 + seg*8);
        }
        cpa_commit();
        cpa_wait0();
        __syncthreads();
        #pragma unroll
        for (int ps = 0; ps < 8; ps++) {
            uint32_t a[2][4];
            ldsm_x4(a[0], aAddr[0] + ps*32);
            ldsm_x4(a[1], aAddr[1] + ps*32);
            uint32_t bb[2*NFN];
            if (NFN == 1) {
                ldsm_x2(bb, bAddr[0] + ps*32);
            } else {
                #pragma unroll
                for (int pg = 0; pg < NFN/2; pg++)
                    ldsm_x4(bb + pg*4, bAddr[pg] + ps*32);
            }
            #pragma unroll
            for (int ni = 0; ni < NFN; ni++) {
                uint32_t b0 = bb[2*ni], b1 = bb[2*ni + 1];
                #pragma unroll
                for (int mi = 0; mi < 2; mi++) mma_bf16(acc[mi][ni], a[mi], b0, b1);
            }
        }
        if (ch + 1 < NCH) __syncthreads();
    }

    // ---- epilogue: bias + per-row per-head l2 norm (head fully within warp) ----
    float sl[2][HPW], sh[2][HPW];
    #pragma unroll
    for (int mi = 0; mi < 2; mi++)
        #pragma unroll
        for (int hh = 0; hh < HPW; hh++) { sl[mi][hh] = 0.f; sh[mi][hh] = 0.f; }
    #pragma unroll
    for (int mi = 0; mi < 2; mi++)
        #pragma unroll
        for (int ni = 0; ni < NFN; ni++) {
            int hh = ni / NH;
            int c0 = cb + ni*8 + 2*tig, c1 = c0 + 1;
            acc[mi][ni][0] += bs_s[c0];
            acc[mi][ni][1] += bs_s[c1];
            acc[mi][ni][2] += bs_s[c0];
            acc[mi][ni][3] += bs_s[c1];
            sl[mi][hh] += acc[mi][ni][0]*acc[mi][ni][0] + acc[mi][ni][1]*acc[mi][ni][1];
            sh[mi][hh] += acc[mi][ni][2]*acc[mi][ni][2] + acc[mi][ni][3]*acc[mi][ni][3];
        }
    #pragma unroll
    for (int mi = 0; mi < 2; mi++)
        #pragma unroll
        for (int hh = 0; hh < HPW; hh++) {
            sl[mi][hh] += __shfl_xor_sync(0xffffffffu, sl[mi][hh], 1);
            sl[mi][hh] += __shfl_xor_sync(0xffffffffu, sl[mi][hh], 2);
            sh[mi][hh] += __shfl_xor_sync(0xffffffffu, sh[mi][hh], 1);
            sh[mi][hh] += __shfl_xor_sync(0xffffffffu, sh[mi][hh], 2);
        }
    float il[2][HPW], ih[2][HPW];
    #pragma unroll
    for (int mi = 0; mi < 2; mi++)
        #pragma unroll
        for (int hh = 0; hh < HPW; hh++) {
            il[mi][hh] = 1.f / fmaxf(sqrtf(sl[mi][hh]), 1e-12f);
            ih[mi][hh] = 1.f / fmaxf(sqrtf(sh[mi][hh]), 1e-12f);
        }

    if (MODE == 0) {
        int bh_out = b*HDIM + hb*HPB + warp_n;
        #pragma unroll
        for (int mi = 0; mi < 2; mi++) {
            int rl = rb + mi*16 + g;
            size_t base_l = ((size_t)bh_out*S + s0 + rl)*DK;
            size_t base_h = ((size_t)bh_out*S + s0 + rl + 8)*DK;
            #pragma unroll
            for (int ni = 0; ni < NFN; ni++) {
                int c0 = ni*8 + 2*tig;
                *(uint32_t*)&d_Knbf[base_l + c0] = packbf(acc[mi][ni][0]*il[mi][0], acc[mi][ni][1]*il[mi][0]);
                *(uint32_t*)&d_Knbf[base_h + c0] = packbf(acc[mi][ni][2]*ih[mi][0], acc[mi][ni][3]*ih[mi][0]);
            }
        }
    } else {
        float* dst = (MODE == 1) ? d_dot2 : d_dot3;
        float dl[2][HPW], dh[2][HPW];
        #pragma unroll
        for (int mi = 0; mi < 2; mi++)
            #pragma unroll
            for (int hh = 0; hh < HPW; hh++) { dl[mi][hh] = 0.f; dh[mi][hh] = 0.f; }
        #pragma unroll
        for (int mi = 0; mi < 2; mi++)
            #pragma unroll
            for (int ni = 0; ni < NFN; ni++) {
                int hh = ni / NH;
                int c0 = cb + ni*8 + 2*tig, c1 = c0 + 1;
                dl[mi][hh] += acc[mi][ni][0]*qs_s[c0] + acc[mi][ni][1]*qs_s[c1];
                dh[mi][hh] += acc[mi][ni][2]*qs_s[c0] + acc[mi][ni][3]*qs_s[c1];
            }
        #pragma unroll
        for (int mi = 0; mi < 2; mi++)
            #pragma unroll
            for (int hh = 0; hh < HPW; hh++) {
                dl[mi][hh] += __shfl_xor_sync(0xffffffffu, dl[mi][hh], 1);
                dl[mi][hh] += __shfl_xor_sync(0xffffffffu, dl[mi][hh], 2);
                dh[mi][hh] += __shfl_xor_sync(0xffffffffu, dh[mi][hh], 1);
                dh[mi][hh] += __shfl_xor_sync(0xffffffffu, dh[mi][hh], 2);
            }
        if (tig == 0) {
            #pragma unroll
            for (int hh = 0; hh < HPW; hh++) {
                int bh_out = b*HDIM + hb*HPB + warp_n*HPW + hh;
                #pragma unroll
                for (int mi = 0; mi < 2; mi++) {
                    int rl = rb + mi*16 + g;
                    int wl = s0 + rl - 31, wh = wl + 8;
                    if (wl >= 0 && wl < Wn) dst[(size_t)bh_out*S + wl] = dl[mi][hh]*il[mi][hh];
                    if (wh >= 0 && wh < Wn) dst[(size_t)bh_out*S + wh] = dh[mi][hh]*ih[mi][hh];
                }
            }
        }
    }
}

// ---------------- banded Qv . Kn -> tn  (bf16 mma, 128-wide tiles) ----------------
__global__ void __launch_bounds__(128) band_mma_kernel(int S, int Wn) {
    constexpr int RS = 36;
    __shared__ uint32_t Qs[32*RS];     // 4608 B
    __shared__ uint32_t Ks[160*RS];    // 23040 B
    __shared__ float Ps[32*160];       // 20480 B
    int tid = threadIdx.x;
    int lane = tid & 31, wid = tid >> 5;
    int g = lane >> 2, tig = lane & 3;
    int w0 = blockIdx.x*128, h = blockIdx.y, b = blockIdx.z;
    int bh = b*HDIM + h;

    uint32_t qB = (uint32_t)__cvta_generic_to_shared(Qs);
    uint32_t kB = (uint32_t)__cvta_generic_to_shared(Ks);

    for (int e = tid; e < 160*8; e += 128) {
        int r = e >> 3, seg = e & 7;
        int s = w0 + r;
        if (s < S) cpa16(kB + (r*RS + seg*4)*4, d_Knbf + ((size_t)bh*S + s)*DK + seg*8);
        else {
            uint32_t* p = &Ks[r*RS + seg*4];
            p[0] = 0; p[1] = 0; p[2] = 0; p[3] = 0;
        }
    }
    for (int e = tid; e < 32*8; e += 128) {
        int r = e >> 3, seg = e & 7;
        cpa16(qB + (r*RS + seg*4)*4, d_Qvbf + ((size_t)bh*MDIM + r)*DK + seg*8);
    }
    cpa_commit();
    cpa_wait0();
    __syncthreads();

    float acc[2][5][4];
    #pragma unroll
    for (int mi = 0; mi < 2; mi++)
        #pragma unroll
        for (int ni = 0; ni < 5; ni++)
            #pragma unroll
            for (int q = 0; q < 4; q++) acc[mi][ni][q] = 0.f;
    int nb = wid*40;
    #pragma unroll
    for (int ks = 0; ks < 4; ks++) {
        int p0 = ks*8;
        uint32_t a[2][4];
        #pragma unroll
        for (int mi = 0; mi < 2; mi++) {
            int r = mi*16 + g;
            a[mi][0] = Qs[r*RS + p0 + tig];
            a[mi][1] = Qs[(r+8)*RS + p0 + tig];
            a[mi][2] = Qs[r*RS + p0 + tig + 4];
            a[mi][3] = Qs[(r+8)*RS + p0 + tig + 4];
        }
        #pragma unroll
        for (int ni = 0; ni < 5; ni++) {
            int cn = nb + ni*8 + g;
            uint32_t b0 = Ks[cn*RS + p0 + tig];
            uint32_t b1 = Ks[cn*RS + p0 + tig + 4];
            #pragma unroll
            for (int mi = 0; mi < 2; mi++) mma_bf16(acc[mi][ni], a[mi], b0, b1);
        }
    }
    #pragma unroll
    for (int mi = 0; mi < 2; mi++)
        #pragma unroll
        for (int ni = 0; ni < 5; ni++) {
            int c0 = nb + ni*8 + 2*tig;
            int r = mi*16 + g;
            Ps[r*160 + c0]     = acc[mi][ni][0];
            Ps[r*160 + c0 + 1] = acc[mi][ni][1];
            Ps[(r+8)*160 + c0]     = acc[mi][ni][2];
            Ps[(r+8)*160 + c0 + 1] = acc[mi][ni][3];
        }
    __syncthreads();
    {
        int w = w0 + tid;
        if (w < Wn) {
            float s = 0.f;
            #pragma unroll
            for (int m = 0; m < 32; m++) s += Ps[m*160 + tid + m];
            d_tn[(size_t)bh*S + w] = s*(1.f/32.f);
        }
    }
}

// ---------------- QA + QP fused (last-row queries, fp32) ----------------
__global__ void qaqp_kernel(const float* __restrict__ aux, const float* __restrict__ Wqa,
                            const float* __restrict__ bqa,
                            const float* __restrict__ pos, const float* __restrict__ Wqp,
                            const float* __restrict__ bqp, int S) {
    int h = blockIdx.x & 7, b = blockIdx.x >> 3;
    int t = threadIdx.x;  // 64
    if (t < 32) {
        int c = t;
        const float* ar = aux + ((size_t)b*S + (S-1))*DA;
        const float* wr = Wqa + ((size_t)h*DAH + c)*DA;
        float acc = bqa[h*DAH + c];
        #pragma unroll 4
        for (int d = 0; d < DA; d++) acc += ar[d]*wr[d];
        float v = acc*acc;
        for (int o = 16; o; o >>= 1) v += __shfl_xor_sync(0xffffffffu, v, o);
        float inv = 1.f / fmaxf(sqrtf(v), 1e-12f);
        d_QA[((size_t)b*HDIM + h)*DAH + c] = acc*inv;
    } else {
        int lane = t - 32;
        int c = lane & 15;
        const float* pr = pos + ((size_t)b*S + (S-1))*DP;
        const float* wr = Wqp + ((size_t)h*DPH + c)*DP;
        float acc = bqp[h*DPH + c];
        #pragma unroll 4
        for (int d = 0; d < DP; d++) acc += pr[d]*wr[d];
        float v = acc*acc;
        for (int o = 8; o; o >>= 1) v += __shfl_xor_sync(0xffffffffu, v, o);
        float inv = 1.f / fmaxf(sqrtf(v), 1e-12f);
        if (lane < 16) d_QP[((size_t)b*HDIM + h)*DPH + c] = acc*inv;
    }
}

// ---------------- online 2-pass softmax over Wn ----------------
__global__ void softmax_kernel(const float* __restrict__ w1, const float* __restrict__ w2,
                               const float* __restrict__ w3, int S, int Wn) {
    int bh = blockIdx.x, t = threadIdx.x;   // 256
    __shared__ float red_m[8], red_l[8];
    __shared__ float fm, fl;
    float c1 = w1[0], c2 = w2[0], c3 = w3[0];
    size_t base = (size_t)bh*S;
    float m = -1e30f, l = 0.f;
    for (int i = t; i < Wn; i += 256) {
        float x = c1*d_tn[base+i] + c2*d_dot2[base+i] + c3*d_dot3[base+i];
        float mn = fmaxf(m, x);
        l = l*__expf(m - mn) + __expf(x - mn);
        m = mn;
    }
    for (int o = 16; o; o >>= 1) {
        float m2 = __shfl_xor_sync(0xffffffffu, m, o);
        float l2 = __shfl_xor_sync(0xffffffffu, l, o);
        float mn = fmaxf(m, m2);
        l = l*__expf(m - mn) + l2*__expf(m2 - mn);
        m = mn;
    }
    if ((t & 31) == 0) { red_m[t >> 5] = m; red_l[t >> 5] = l; }
    __syncthreads();
    if (t == 0) {
        float M = red_m[0], L = red_l[0];
        for (int i = 1; i < 8; i++) {
            float mn = fmaxf(M, red_m[i]);
            L = L*__expf(M - mn) + red_l[i]*__expf(red_m[i] - mn);
            M = mn;
        }
        fm = M; fl = L;
    }
    __syncthreads();
    float MX = fm, inv = 1.f/fl;
    for (int i = t; i < Wn; i += 256) {
        float x = c1*d_tn[base+i] + c2*d_dot2[base+i] + c3*d_dot3[base+i];
        float a = __expf(x - MX)*inv;
        d_attn[base+i] = a;
        if (i == Wn-1) d_alast[bh] = a;
    }
}

// ---------------- xbar: attn-weighted row sums of x (bf16 X) ----------------
__global__ void xbar_kernel(int S, int Wn) {
    __shared__ float a_s[8][64];
    int t = threadIdx.x;                 // 256
    int w0 = blockIdx.x*64, b = blockIdx.y;
    for (int i = t; i < 512; i += 256) {
        int hh = i >> 6, j = i & 63;
        int w = w0 + j;
        a_s[hh][j] = (w < Wn-1) ? d_attn[((size_t)b*HDIM + hh)*S + w] : 0.f;
    }
    __syncthreads();
    float acc[8][2];
    #pragma unroll
    for (int h = 0; h < 8; h++) { acc[h][0] = 0.f; acc[h][1] = 0.f; }
    int nrow = Wn - 1 - w0; if (nrow > 64) nrow = 64;
    for (int j = 0; j < nrow; j++) {
        const __nv_bfloat16* xr = d_Xbf + ((size_t)b*S + (31 + w0 + j))*DM;
        float x0 = __bfloat162float(xr[t]);
        float x1 = __bfloat162float(xr[256 + t]);
        #pragma unroll
        for (int h = 0; h < 8; h++) {
            float a = a_s[h][j];
            acc[h][0] += a*x0;
            acc[h][1] += a*x1;
        }
    }
    #pragma unroll
    for (int h = 0; h < 8; h++) {
        atomicAdd(&d_xbar[((size_t)b*HDIM + h)*DM + t], acc[h][0]);
        atomicAdd(&d_xbar[((size_t)b*HDIM + h)*DM + 256 + t], acc[h][1]);
    }
}

// ---------------- GRU ----------------
__global__ void gi_kernel(const float* __restrict__ memory, const float* __restrict__ b_ih,
                          int S) {
    int tt = blockIdx.x, b = blockIdx.y;
    __shared__ float xs[DM];
    int s = S - MDIM + tt;
    const float* row = memory + ((size_t)b*(S-1) + s)*DM;
    for (int i = threadIdx.x; i < DM; i += 192) xs[i] = row[i];
    __syncthreads();
    int j = threadIdx.x;
    float acc = b_ih[j];
    #pragma unroll 8
    for (int d = 0; d < DM; d++) acc += xs[d]*d_WihT[d*192 + j];
    d_gi[((size_t)b*31 + tt)*192 + j] = acc;
}

__global__ void gru_kernel(const float* __restrict__ b_hh) {
    int b = blockIdx.x, j = threadIdx.x;  // 192
    __shared__ float hs[DK];
    __shared__ float gh_s[192];
    if (j < DK) hs[j] = 0.f;
    __syncthreads();
    float bh = b_hh[j];
    for (int t = 0; t < 31; t++) {
        float gh = bh;
        #pragma unroll 8
        for (int k2 = 0; k2 < DK; k2++) gh += hs[k2]*d_WhhT[k2*192 + j];
        gh_s[j] = gh;
        __syncthreads();
        float hn = 0.f;
        if (j < DK) {
            const float* gi = d_gi + ((size_t)b*31 + t)*192;
            float r = 1.f/(1.f + __expf(-(gi[j] + gh_s[j])));
            float z = 1.f/(1.f + __expf(-(gi[64 + j] + gh_s[64 + j])));
            float n = tanhf(gi[128 + j] + r*gh_s[128 + j]);
            hn = (1.f - z)*n + z*hs[j];
        }
        __syncthreads();
        if (j < DK) hs[j] = hn;
        __syncthreads();
    }
    if (j < DK) d_res[b*DK + j] = hs[j];
}

// ---------------- fused deta + out ----------------
__global__ void __launch_bounds__(512) detaout_kernel(const float* __restrict__ bv,
                               const float* __restrict__ x_pre, const float* __restrict__ bO,
                               float* __restrict__ out) {
    int b = blockIdx.x, t = threadIdx.x;  // 512
    __shared__ float xb[8][DM];
    __shared__ float dd[DM];
    for (int i = t; i < 8*DM; i += 512)
        xb[i >> 9][i & 511] = d_xbar[(size_t)(b*HDIM + (i >> 9))*DM + (i & 511)];
    __syncthreads();
    int h = t >> 6, c = t & 63;
    const float* wt = d_WvMT + (size_t)h*DM*DK;
    float acc = 0.f;
    #pragma unroll 8
    for (int d = 0; d < DM; d++) acc += xb[h][d]*wt[d*DK + c];
    float al = d_alast[b*HDIM + h];
    dd[t] = acc + bv[h*DK + c]*(1.f - al) + al*d_res[b*DK + c];
    __syncthreads();
    float o = bO[t];
    #pragma unroll 8
    for (int i = 0; i < DM; i++) o += dd[i]*d_WOMT[(size_t)i*DM + t];
    out[(size_t)b*DM + t] = x_pre[(size_t)b*DM + t] + o;
}

extern "C" void kernel_launch(void* const* d_in, const int* in_sizes, int n_in,
                              void* d_out, int out_size) {
    const float* memory = (const float*)d_in[0];
    const float* x_pre  = (const float*)d_in[1];
    const float* aux    = (const float*)d_in[2];
    const float* pos    = (const float*)d_in[3];
    const float* Wq  = (const float*)d_in[4];
    const float* bq  = (const float*)d_in[5];
    const float* Wk  = (const float*)d_in[6];
    const float* bk  = (const float*)d_in[7];
    const float* Wv  = (const float*)d_in[8];
    const float* bv  = (const float*)d_in[9];
    const float* Wqa = (const float*)d_in[10];
    const float* bqa = (const float*)d_in[11];
    const float* Wka = (const float*)d_in[12];
    const float* bka = (const float*)d_in[13];
    const float* Wqp = (const float*)d_in[14];
    const float* bqp = (const float*)d_in[15];
    const float* Wkp = (const float*)d_in[16];
    const float* bkp = (const float*)d_in[17];
    const float* W_ih = (const float*)d_in[18];
    const float* W_hh = (const float*)d_in[19];
    const float* b_ih = (const float*)d_in[20];
    const float* b_hh = (const float*)d_in[21];
    const float* WO = (const float*)d_in[22];
    const float* bO = (const float*)d_in[23];
    const float* w   = (const float*)d_in[24];
    const float* w_a = (const float*)d_in[25];
    const float* w_p = (const float*)d_in[26];
    const int* G = (const int*)d_in[27];
    float* out = (float*)d_out;

    int S  = in_sizes[2] / (BDIM*DA);   // 6144
    int Wn = S - MDIM + 1;              // 6113

    __nv_bfloat16 *Xbf_p, *Abf_p, *Pbf_p, *WkMbf_p, *Wkabf_p, *Wkpbf_p;
    cudaGetSymbolAddress((void**)&Xbf_p, d_Xbf);
    cudaGetSymbolAddress((void**)&Abf_p, d_Abf);
    cudaGetSymbolAddress((void**)&Pbf_p, d_Pbf);
    cudaGetSymbolAddress((void**)&WkMbf_p, d_WkMbf);
    cudaGetSymbolAddress((void**)&Wkabf_p, d_Wkabf);
    cudaGetSymbolAddress((void**)&Wkpbf_p, d_Wkpbf);

    const int smem_k = (128 + 128)*68*4;   // 69632
    const int smem_a = (128 + 128)*68*4;   // 69632
    const int smem_p = (128 + 64)*68*4;    // 52224
    cudaFuncSetAttribute(proj_mma_kernel<DM, 128, 0, 1>,
                         cudaFuncAttributeMaxDynamicSharedMemorySize, smem_k);
    cudaFuncSetAttribute(proj_mma_kernel<DA, 128, 1, 2>,
                         cudaFuncAttributeMaxDynamicSharedMemorySize, smem_a);
    cudaFuncSetAttribute(proj_mma_kernel<DP, 64, 2, 2>,
                         cudaFuncAttributeMaxDynamicSharedMemorySize, smem_p);

    convert_kernel<<<dim3(512, BDIM), 256>>>(memory, x_pre, aux, pos, S);
    mask_kernel<<<1024, 256>>>(Wq, Wk, Wv, WO, W_ih, W_hh, Wka, Wkp, G);
    qv_kernel<<<BDIM*HDIM*8, 256>>>(memory, x_pre, bq, S);
    proj_mma_kernel<DM, 128, 0, 1><<<dim3(S/128, HDIM/2, BDIM), 256, smem_k>>>(Xbf_p, WkMbf_p, bk, S, Wn);
    band_mma_kernel<<<dim3((Wn + 127)/128, HDIM, BDIM), 128>>>(S, Wn);
    qaqp_kernel<<<BDIM*HDIM, 64>>>(aux, Wqa, bqa, pos, Wqp, bqp, S);
    proj_mma_kernel<DA, 128, 1, 2><<<dim3(S/128, HDIM/4, BDIM), 256, smem_a>>>(Abf_p, Wkabf_p, bka, S, Wn);
    proj_mma_kernel<DP, 64, 2, 2><<<dim3(S/128, HDIM/4, BDIM), 256, smem_p>>>(Pbf_p, Wkpbf_p, bkp, S, Wn);
    softmax_kernel<<<BDIM*HDIM, 256>>>(w, w_a, w_p, S, Wn);
    xbar_kernel<<<dim3((Wn - 1 + 63)/64, BDIM), 256>>>(S, Wn);
    gi_kernel<<<dim3(31, BDIM), 192>>>(memory, b_ih, S);
    gru_kernel<<<BDIM, 192>>>(b_hh);
    detaout_kernel<<<BDIM, 512>>>(bv, x_pre, bO, out);
}

// round 16
// speedup vs baseline: 1.1775x; 1.1775x over previous
#include <cuda_runtime.h>
#include <cuda_bf16.h>
#include <math.h>
#include <stdint.h>
#include <stddef.h>

// fixed problem shapes
#define BDIM 8
#define HDIM 8
#define DM 512
#define DA 256
#define DP 128
#define MDIM 32
#define DK 64
#define DAH 32
#define DPH 16
#define SDIM 6144

// ---------------- device scratch ----------------
__device__ __nv_bfloat16 d_Xbf[(size_t)BDIM*SDIM*DM];
__device__ __nv_bfloat16 d_Abf[(size_t)BDIM*SDIM*DA];
__device__ __nv_bfloat16 d_Pbf[(size_t)BDIM*SDIM*DP];
__device__ __nv_bfloat16 d_WkMbf[HDIM*DK*DM];
__device__ __nv_bfloat16 d_Wkabf[HDIM*DAH*DA];
__device__ __nv_bfloat16 d_Wkpbf[HDIM*DPH*DP];
__device__ float d_WqMT[HDIM*DM*DK];
__device__ float d_WvMT[HDIM*DM*DK];
__device__ float d_WOMT[DM*DM];
__device__ float d_WihT[DM*192];
__device__ float d_WhhT[DK*192];
__device__ __nv_bfloat16 d_Knbf[(size_t)BDIM*HDIM*SDIM*DK];
__device__ __nv_bfloat16 d_Qvbf[BDIM*HDIM*MDIM*DK];
__device__ float d_QA[BDIM*HDIM*DAH];
__device__ float d_QP[BDIM*HDIM*DPH];
__device__ float d_tn[BDIM*HDIM*SDIM];
__device__ float d_dot2[BDIM*HDIM*SDIM];
__device__ float d_dot3[BDIM*HDIM*SDIM];
__device__ float d_attn[BDIM*HDIM*SDIM];
__device__ float d_alast[BDIM*HDIM];
__device__ float d_xbar[BDIM*HDIM*DM];
__device__ float d_gi[BDIM*31*192];
__device__ float d_res[BDIM*DK];

__device__ __forceinline__ void mma_bf16(float* c, const uint32_t* a, uint32_t b0, uint32_t b1) {
    asm volatile("mma.sync.aligned.m16n8k16.row.col.f32.bf16.bf16.f32 "
        "{%0,%1,%2,%3}, {%4,%5,%6,%7}, {%8,%9}, {%0,%1,%2,%3};\n"
        : "+f"(c[0]), "+f"(c[1]), "+f"(c[2]), "+f"(c[3])
        : "r"(a[0]), "r"(a[1]), "r"(a[2]), "r"(a[3]), "r"(b0), "r"(b1));
}

__device__ __forceinline__ void ldsm_x4(uint32_t* r, uint32_t addr) {
    asm volatile("ldmatrix.sync.aligned.m8n8.x4.shared.b16 {%0,%1,%2,%3}, [%4];"
        : "=r"(r[0]), "=r"(r[1]), "=r"(r[2]), "=r"(r[3]) : "r"(addr));
}
__device__ __forceinline__ void ldsm_x2(uint32_t* r, uint32_t addr) {
    asm volatile("ldmatrix.sync.aligned.m8n8.x2.shared.b16 {%0,%1}, [%2];"
        : "=r"(r[0]), "=r"(r[1]) : "r"(addr));
}

__device__ __forceinline__ void cpa16(uint32_t saddr, const void* g) {
    asm volatile("cp.async.cg.shared.global [%0], [%1], 16;" :: "r"(saddr), "l"(g));
}
__device__ __forceinline__ void cpa_commit() { asm volatile("cp.async.commit_group;"); }
__device__ __forceinline__ void cpa_wait0() { asm volatile("cp.async.wait_group 0;" ::: "memory"); }

__device__ __forceinline__ uint32_t packbf(float a, float b) {
    __nv_bfloat162 t = __floats2bfloat162_rn(a, b);
    return *(uint32_t*)&t;
}

// ---------------- fp32 -> bf16 conversion (2D grid, shift indexing) ----------------
__global__ void __launch_bounds__(256) convert_kernel(
        const float* __restrict__ memory, const float* __restrict__ x_pre,
        const float* __restrict__ aux, const float* __restrict__ pos, int S) {
    int b = blockIdx.y;
    int stride = gridDim.x*256;
    int t0 = blockIdx.x*256 + threadIdx.x;
    int nX = S << 7;
    const float* memB = memory + (size_t)b*(S-1)*DM;
    __nv_bfloat16* XB = d_Xbf + (size_t)b*S*DM;
    for (int j = t0; j < nX; j += stride) {
        int s = j >> 7, d4 = (j & 127) << 2;
        const float* src = (s < S-1) ? memB + ((size_t)s << 9) + d4 : x_pre + ((size_t)b << 9) + d4;
        float4 v = *(const float4*)src;
        uint2 o; o.x = packbf(v.x, v.y); o.y = packbf(v.z, v.w);
        *(uint2*)&XB[((size_t)s << 9) + d4] = o;
    }
    int nA = S << 6;
    const float* auxB = aux + (size_t)b*S*DA;
    __nv_bfloat16* AB = d_Abf + (size_t)b*S*DA;
    for (int j = t0; j < nA; j += stride) {
        float4 v = *(const float4*)(auxB + ((size_t)j << 2));
        uint2 o; o.x = packbf(v.x, v.y); o.y = packbf(v.z, v.w);
        *(uint2*)&AB[(size_t)j << 2] = o;
    }
    int nP = S << 5;
    const float* posB = pos + (size_t)b*S*DP;
    __nv_bfloat16* PB = d_Pbf + (size_t)b*S*DP;
    for (int j = t0; j < nP; j += stride) {
        float4 v = *(const float4*)(posB + ((size_t)j << 2));
        uint2 o; o.x = packbf(v.x, v.y); o.y = packbf(v.z, v.w);
        *(uint2*)&PB[(size_t)j << 2] = o;
    }
}

// ---------------- masked weights (+ transposes, bf16 copies) + zero xbar ----------------
__global__ void mask_kernel(const float* __restrict__ Wq, const float* __restrict__ Wk,
                            const float* __restrict__ Wv, const float* __restrict__ WO,
                            const float* __restrict__ W_ih, const float* __restrict__ W_hh,
                            const float* __restrict__ Wka, const float* __restrict__ Wkp,
                            const int* __restrict__ G) {
    int i = blockIdx.x*256 + threadIdx.x;
    const int NW = HDIM*DK*DM;
    if (i < NW) {
        int h = i >> 15;
        int c = (i >> 9) & 63;
        int d = i & 511;
        float g = (float)G[c*64 + (d & 63)];
        d_WkMbf[i] = __float2bfloat16(Wk[i]*g);
        d_WqMT[((size_t)h*DM + d)*DK + c] = Wq[i]*g;
        d_WvMT[((size_t)h*DM + d)*DK + c] = Wv[i]*g;
    }
    if (i < HDIM*DAH*DA) d_Wkabf[i] = __float2bfloat16(Wka[i]);
    if (i < HDIM*DPH*DP) d_Wkpbf[i] = __float2bfloat16(Wkp[i]);
    if (i < DM*DM) {
        int j = i & 511, r = i >> 9;
        d_WOMT[(size_t)j*DM + r] = WO[i]*(float)G[(r & 63)*64 + (j & 63)];
    }
    if (i < 192*DM) {
        int j = i >> 9, d = i & 511;
        d_WihT[d*192 + j] = W_ih[i];
    }
    if (i < 192*DK) {
        int j = i >> 6, k = i & 63;
        d_WhhT[k*192 + j] = W_hh[i];
    }
    if (i < BDIM*HDIM*DM) d_xbar[i] = 0.f;
}

// ---------------- Qv: last M rows (4 rows per block), masked proj + l2norm ----------------
__global__ void __launch_bounds__(256) qv_kernel(const float* __restrict__ memory,
                          const float* __restrict__ x_pre,
                          const float* __restrict__ bq, int S) {
    int mgrp = blockIdx.x & 7, h = (blockIdx.x >> 3) & 7, b = blockIdx.x >> 6;
    __shared__ float xs[4][DM];
    __shared__ float wp[4][2];
    int tid = threadIdx.x;
    int mg = tid >> 6, c = tid & 63;
    for (int i = tid; i < 4*DM; i += 256) {
        int r = i >> 9, d = i & 511;
        int s = S - MDIM + mgrp*4 + r;
        const float* row = (s < S-1) ? memory + ((size_t)b*(S-1) + s)*DM : x_pre + (size_t)b*DM;
        xs[r][d] = row[d];
    }
    __syncthreads();
    const float* wt = d_WqMT + (size_t)h*DM*DK;
    float acc = bq[h*DK + c];
    #pragma unroll 8
    for (int d = 0; d < DM; d++) acc += xs[mg][d]*wt[d*DK + c];
    float v = acc*acc;
    for (int o = 16; o; o >>= 1) v += __shfl_xor_sync(0xffffffffu, v, o);
    if ((tid & 31) == 0) wp[mg][(c >> 5)] = v;
    __syncthreads();
    float inv = 1.f / fmaxf(sqrtf(wp[mg][0] + wp[mg][1]), 1e-12f);
    int m = mgrp*4 + mg;
    d_Qvbf[(((size_t)b*HDIM + h)*MDIM + m)*DK + c] = __float2bfloat16(acc*inv);
}

// ---------------- tensor-core projection: 2 heads per block, warp_n = local head ----------------
template<int DIN, int DOUT, int MODE>
__global__ void __launch_bounds__(256)
proj_mma_kernel(const __nv_bfloat16* __restrict__ src, const __nv_bfloat16* __restrict__ W,
                const float* __restrict__ bias, int S, int Wn) {
    constexpr int NW_N = 2;
    constexpr int TM   = 128;
    constexpr int WT_N = DOUT/NW_N;
    constexpr int NFN  = WT_N/8;
    constexpr int KC   = 128;
    constexpr int NCH  = DIN/KC;
    constexpr int RS   = 68;

    extern __shared__ uint32_t dynsm[];
    uint32_t* Xs  = dynsm;
    uint32_t* Wss = dynsm + TM*RS;
    __shared__ float bs_s[DOUT];
    __shared__ float qs_s[DOUT];

    int tid = threadIdx.x;
    int lane = tid & 31, wid = tid >> 5;
    int g = lane >> 2, tig = lane & 3;
    int warp_n = wid % NW_N, warp_m = wid / NW_N;
    int rb = warp_m*32, cb = warp_n*WT_N;
    int s0 = blockIdx.x*TM, hb = blockIdx.y, b = blockIdx.z;

    uint32_t xB = (uint32_t)__cvta_generic_to_shared(Xs);
    uint32_t wB = (uint32_t)__cvta_generic_to_shared(Wss);

    uint32_t aAddr[2];
    #pragma unroll
    for (int mi = 0; mi < 2; mi++)
        aAddr[mi] = xB + ((rb + mi*16 + (lane & 7) + (lane & 8))*RS + ((lane >> 4) & 1)*4)*4;
    uint32_t bAddr[(NFN + 1)/2];
    #pragma unroll
    for (int pg = 0; pg < (NFN + 1)/2; pg++) {
        if (NFN == 1)
            bAddr[pg] = wB + ((cb + (lane & 7))*RS + ((lane >> 3) & 1)*4)*4;
        else
            bAddr[pg] = wB + ((cb + pg*16 + ((lane >> 4) & 1)*8 + (lane & 7))*RS + ((lane >> 3) & 1)*4)*4;
    }

    for (int i = tid; i < DOUT; i += 256) {
        bs_s[i] = bias[hb*DOUT + i];
        if (MODE == 1) qs_s[i] = d_QA[(size_t)(b*HDIM + hb*2 + (i >> 5))*DAH + (i & 31)];
        if (MODE == 2) qs_s[i] = d_QP[(size_t)(b*HDIM + hb*2 + (i >> 4))*DPH + (i & 15)];
    }

    float acc[2][NFN][4];
    #pragma unroll
    for (int mi = 0; mi < 2; mi++)
        #pragma unroll
        for (int ni = 0; ni < NFN; ni++)
            #pragma unroll
            for (int q = 0; q < 4; q++) acc[mi][ni][q] = 0.f;

    for (int ch = 0; ch < NCH; ch++) {
        int d0 = ch*KC;
        #pragma unroll
        for (int it = 0; it < TM*16/256; it++) {
            int e = it*256 + tid;
            int row = e >> 4, seg = e & 15;
            cpa16(xB + (row*RS + seg*4)*4, src + ((size_t)b*S + s0 + row)*DIN + d0 + seg*8);
        }
        for (int e = tid; e < DOUT*16; e += 256) {
            int rr = e >> 4, seg = e & 15;
            cpa16(wB + (rr*RS + seg*4)*4, W + ((size_t)(hb*DOUT + rr))*DIN + d0 + seg*8);
        }
        cpa_commit();
        cpa_wait0();
        __syncthreads();
        #pragma unroll
        for (int ps = 0; ps < 8; ps++) {
            uint32_t a[2][4];
            ldsm_x4(a[0], aAddr[0] + ps*32);
            ldsm_x4(a[1], aAddr[1] + ps*32);
            uint32_t bb[2*NFN];
            if (NFN == 1) {
                ldsm_x2(bb, bAddr[0] + ps*32);
            } else {
                #pragma unroll
                for (int pg = 0; pg < NFN/2; pg++)
                    ldsm_x4(bb + pg*4, bAddr[pg] + ps*32);
            }
            #pragma unroll
            for (int ni = 0; ni < NFN; ni++) {
                uint32_t b0 = bb[2*ni], b1 = bb[2*ni + 1];
                #pragma unroll
                for (int mi = 0; mi < 2; mi++) mma_bf16(acc[mi][ni], a[mi], b0, b1);
            }
        }
        if (ch + 1 < NCH) __syncthreads();
    }

    // ---- epilogue: bias + per-row per-head (per-warp) l2 norm ----
    float sl[2] = {0.f, 0.f}, sh[2] = {0.f, 0.f};
    #pragma unroll
    for (int mi = 0; mi < 2; mi++)
        #pragma unroll
        for (int ni = 0; ni < NFN; ni++) {
            int c0 = cb + ni*8 + 2*tig, c1 = c0 + 1;
            acc[mi][ni][0] += bs_s[c0];
            acc[mi][ni][1] += bs_s[c1];
            acc[mi][ni][2] += bs_s[c0];
            acc[mi][ni][3] += bs_s[c1];
            sl[mi] += acc[mi][ni][0]*acc[mi][ni][0] + acc[mi][ni][1]*acc[mi][ni][1];
            sh[mi] += acc[mi][ni][2]*acc[mi][ni][2] + acc[mi][ni][3]*acc[mi][ni][3];
        }
    #pragma unroll
    for (int mi = 0; mi < 2; mi++) {
        sl[mi] += __shfl_xor_sync(0xffffffffu, sl[mi], 1);
        sl[mi] += __shfl_xor_sync(0xffffffffu, sl[mi], 2);
        sh[mi] += __shfl_xor_sync(0xffffffffu, sh[mi], 1);
        sh[mi] += __shfl_xor_sync(0xffffffffu, sh[mi], 2);
    }
    float il[2], ih[2];
    #pragma unroll
    for (int mi = 0; mi < 2; mi++) {
        il[mi] = 1.f / fmaxf(sqrtf(sl[mi]), 1e-12f);
        ih[mi] = 1.f / fmaxf(sqrtf(sh[mi]), 1e-12f);
    }

    int bh_out = b*HDIM + hb*2 + warp_n;
    if (MODE == 0) {
        #pragma unroll
        for (int mi = 0; mi < 2; mi++) {
            int rl = rb + mi*16 + g;
            size_t base_l = ((size_t)bh_out*S + s0 + rl)*DK;
            size_t base_h = ((size_t)bh_out*S + s0 + rl + 8)*DK;
            #pragma unroll
            for (int ni = 0; ni < NFN; ni++) {
                int c0 = ni*8 + 2*tig;
                *(uint32_t*)&d_Knbf[base_l + c0] = packbf(acc[mi][ni][0]*il[mi], acc[mi][ni][1]*il[mi]);
                *(uint32_t*)&d_Knbf[base_h + c0] = packbf(acc[mi][ni][2]*ih[mi], acc[mi][ni][3]*ih[mi]);
            }
        }
    } else {
        float* dst = (MODE == 1) ? d_dot2 : d_dot3;
        float dl[2], dh[2];
        #pragma unroll
        for (int mi = 0; mi < 2; mi++) {
            dl[mi] = 0.f; dh[mi] = 0.f;
            #pragma unroll
            for (int ni = 0; ni < NFN; ni++) {
                int c0 = cb + ni*8 + 2*tig, c1 = c0 + 1;
                dl[mi] += acc[mi][ni][0]*qs_s[c0] + acc[mi][ni][1]*qs_s[c1];
                dh[mi] += acc[mi][ni][2]*qs_s[c0] + acc[mi][ni][3]*qs_s[c1];
            }
            dl[mi] += __shfl_xor_sync(0xffffffffu, dl[mi], 1);
            dl[mi] += __shfl_xor_sync(0xffffffffu, dl[mi], 2);
            dh[mi] += __shfl_xor_sync(0xffffffffu, dh[mi], 1);
            dh[mi] += __shfl_xor_sync(0xffffffffu, dh[mi], 2);
        }
        if (tig == 0) {
            #pragma unroll
            for (int mi = 0; mi < 2; mi++) {
                int rl = rb + mi*16 + g;
                int wl = s0 + rl - 31, wh = wl + 8;
                if (wl >= 0 && wl < Wn) dst[(size_t)bh_out*S + wl] = dl[mi]*il[mi];
                if (wh >= 0 && wh < Wn) dst[(size_t)bh_out*S + wh] = dh[mi]*ih[mi];
            }
        }
    }
}

// ---------------- banded Qv . Kn -> tn  (bf16 mma, 64-wide tiles) ----------------
__global__ void __launch_bounds__(128) band_mma_kernel(int S, int Wn) {
    constexpr int RS = 36;
    __shared__ uint32_t Qs[32*RS];
    __shared__ uint32_t Ks[96*RS];
    __shared__ float Ps[32*100];
    int tid = threadIdx.x;
    int lane = tid & 31, wid = tid >> 5;
    int g = lane >> 2, tig = lane & 3;
    int w0 = blockIdx.x*64, h = blockIdx.y, b = blockIdx.z;
    int bh = b*HDIM + h;

    uint32_t qB = (uint32_t)__cvta_generic_to_shared(Qs);
    uint32_t kB = (uint32_t)__cvta_generic_to_shared(Ks);

    for (int e = tid; e < 96*8; e += 128) {
        int r = e >> 3, seg = e & 7;
        int s = w0 + r;
        if (s < S) cpa16(kB + (r*RS + seg*4)*4, d_Knbf + ((size_t)bh*S + s)*DK + seg*8);
        else {
            uint32_t* p = &Ks[r*RS + seg*4];
            p[0] = 0; p[1] = 0; p[2] = 0; p[3] = 0;
        }
    }
    for (int e = tid; e < 32*8; e += 128) {
        int r = e >> 3, seg = e & 7;
        cpa16(qB + (r*RS + seg*4)*4, d_Qvbf + ((size_t)bh*MDIM + r)*DK + seg*8);
    }
    cpa_commit();
    cpa_wait0();
    __syncthreads();

    float acc[2][3][4];
    #pragma unroll
    for (int mi = 0; mi < 2; mi++)
        #pragma unroll
        for (int ni = 0; ni < 3; ni++)
            #pragma unroll
            for (int q = 0; q < 4; q++) acc[mi][ni][q] = 0.f;
    int nb = wid*24;
    #pragma unroll
    for (int ks = 0; ks < 4; ks++) {
        int p0 = ks*8;
        uint32_t a[2][4];
        #pragma unroll
        for (int mi = 0; mi < 2; mi++) {
            int r = mi*16 + g;
            a[mi][0] = Qs[r*RS + p0 + tig];
            a[mi][1] = Qs[(r+8)*RS + p0 + tig];
            a[mi][2] = Qs[r*RS + p0 + tig + 4];
            a[mi][3] = Qs[(r+8)*RS + p0 + tig + 4];
        }
        #pragma unroll
        for (int ni = 0; ni < 3; ni++) {
            int cn = nb + ni*8 + g;
            uint32_t b0 = Ks[cn*RS + p0 + tig];
            uint32_t b1 = Ks[cn*RS + p0 + tig + 4];
            #pragma unroll
            for (int mi = 0; mi < 2; mi++) mma_bf16(acc[mi][ni], a[mi], b0, b1);
        }
    }
    #pragma unroll
    for (int mi = 0; mi < 2; mi++)
        #pragma unroll
        for (int ni = 0; ni < 3; ni++) {
            int c0 = nb + ni*8 + 2*tig;
            int r = mi*16 + g;
            Ps[r*100 + c0]     = acc[mi][ni][0];
            Ps[r*100 + c0 + 1] = acc[mi][ni][1];
            Ps[(r+8)*100 + c0]     = acc[mi][ni][2];
            Ps[(r+8)*100 + c0 + 1] = acc[mi][ni][3];
        }
    __syncthreads();
    if (tid < 64) {
        int w = w0 + tid;
        if (w < Wn) {
            float s = 0.f;
            #pragma unroll
            for (int m = 0; m < 32; m++) s += Ps[m*100 + tid + m];
            d_tn[(size_t)bh*S + w] = s*(1.f/32.f);
        }
    }
}

// ---------------- QA + QP fused (last-row queries, fp32) ----------------
__global__ void qaqp_kernel(const float* __restrict__ aux, const float* __restrict__ Wqa,
                            const float* __restrict__ bqa,
                            const float* __restrict__ pos, const float* __restrict__ Wqp,
                            const float* __restrict__ bqp, int S) {
    int h = blockIdx.x & 7, b = blockIdx.x >> 3;
    int t = threadIdx.x;  // 64
    if (t < 32) {
        int c = t;
        const float* ar = aux + ((size_t)b*S + (S-1))*DA;
        const float* wr = Wqa + ((size_t)h*DAH + c)*DA;
        float acc = bqa[h*DAH + c];
        #pragma unroll 4
        for (int d = 0; d < DA; d++) acc += ar[d]*wr[d];
        float v = acc*acc;
        for (int o = 16; o; o >>= 1) v += __shfl_xor_sync(0xffffffffu, v, o);
        float inv = 1.f / fmaxf(sqrtf(v), 1e-12f);
        d_QA[((size_t)b*HDIM + h)*DAH + c] = acc*inv;
    } else {
        int lane = t - 32;
        int c = lane & 15;
        const float* pr = pos + ((size_t)b*S + (S-1))*DP;
        const float* wr = Wqp + ((size_t)h*DPH + c)*DP;
        float acc = bqp[h*DPH + c];
        #pragma unroll 4
        for (int d = 0; d < DP; d++) acc += pr[d]*wr[d];
        float v = acc*acc;
        for (int o = 8; o; o >>= 1) v += __shfl_xor_sync(0xffffffffu, v, o);
        float inv = 1.f / fmaxf(sqrtf(v), 1e-12f);
        if (lane < 16) d_QP[((size_t)b*HDIM + h)*DPH + c] = acc*inv;
    }
}

// ---------------- online 2-pass softmax over Wn ----------------
__global__ void softmax_kernel(const float* __restrict__ w1, const float* __restrict__ w2,
                               const float* __restrict__ w3, int S, int Wn) {
    int bh = blockIdx.x, t = threadIdx.x;   // 256
    __shared__ float red_m[8], red_l[8];
    __shared__ float fm, fl;
    float c1 = w1[0], c2 = w2[0], c3 = w3[0];
    size_t base = (size_t)bh*S;
    float m = -1e30f, l = 0.f;
    for (int i = t; i < Wn; i += 256) {
        float x = c1*d_tn[base+i] + c2*d_dot2[base+i] + c3*d_dot3[base+i];
        float mn = fmaxf(m, x);
        l = l*__expf(m - mn) + __expf(x - mn);
        m = mn;
    }
    for (int o = 16; o; o >>= 1) {
        float m2 = __shfl_xor_sync(0xffffffffu, m, o);
        float l2 = __shfl_xor_sync(0xffffffffu, l, o);
        float mn = fmaxf(m, m2);
        l = l*__expf(m - mn) + l2*__expf(m2 - mn);
        m = mn;
    }
    if ((t & 31) == 0) { red_m[t >> 5] = m; red_l[t >> 5] = l; }
    __syncthreads();
    if (t == 0) {
        float M = red_m[0], L = red_l[0];
        for (int i = 1; i < 8; i++) {
            float mn = fmaxf(M, red_m[i]);
            L = L*__expf(M - mn) + red_l[i]*__expf(red_m[i] - mn);
            M = mn;
        }
        fm = M; fl = L;
    }
    __syncthreads();
    float MX = fm, inv = 1.f/fl;
    for (int i = t; i < Wn; i += 256) {
        float x = c1*d_tn[base+i] + c2*d_dot2[base+i] + c3*d_dot3[base+i];
        float a = __expf(x - MX)*inv;
        d_attn[base+i] = a;
        if (i == Wn-1) d_alast[bh] = a;
    }
}

// ---------------- xbar: attn-weighted row sums of x (bf16 X) ----------------
__global__ void xbar_kernel(int S, int Wn) {
    __shared__ float a_s[8][64];
    int t = threadIdx.x;                 // 256
    int w0 = blockIdx.x*64, b = blockIdx.y;
    for (int i = t; i < 512; i += 256) {
        int hh = i >> 6, j = i & 63;
        int w = w0 + j;
        a_s[hh][j] = (w < Wn-1) ? d_attn[((size_t)b*HDIM + hh)*S + w] : 0.f;
    }
    __syncthreads();
    float acc[8][2];
    #pragma unroll
    for (int h = 0; h < 8; h++) { acc[h][0] = 0.f; acc[h][1] = 0.f; }
    int nrow = Wn - 1 - w0; if (nrow > 64) nrow = 64;
    for (int j = 0; j < nrow; j++) {
        const __nv_bfloat16* xr = d_Xbf + ((size_t)b*S + (31 + w0 + j))*DM;
        float x0 = __bfloat162float(xr[t]);
        float x1 = __bfloat162float(xr[256 + t]);
        #pragma unroll
        for (int h = 0; h < 8; h++) {
            float a = a_s[h][j];
            acc[h][0] += a*x0;
            acc[h][1] += a*x1;
        }
    }
    #pragma unroll
    for (int h = 0; h < 8; h++) {
        atomicAdd(&d_xbar[((size_t)b*HDIM + h)*DM + t], acc[h][0]);
        atomicAdd(&d_xbar[((size_t)b*HDIM + h)*DM + 256 + t], acc[h][1]);
    }
}

// ---------------- GRU ----------------
__global__ void gi_kernel(const float* __restrict__ memory, const float* __restrict__ b_ih,
                          int S) {
    int tt = blockIdx.x, b = blockIdx.y;
    __shared__ float xs[DM];
    int s = S - MDIM + tt;
    const float* row = memory + ((size_t)b*(S-1) + s)*DM;
    for (int i = threadIdx.x; i < DM; i += 192) xs[i] = row[i];
    __syncthreads();
    int j = threadIdx.x;
    float acc = b_ih[j];
    #pragma unroll 8
    for (int d = 0; d < DM; d++) acc += xs[d]*d_WihT[d*192 + j];
    d_gi[((size_t)b*31 + tt)*192 + j] = acc;
}

__global__ void gru_kernel(const float* __restrict__ b_hh) {
    int b = blockIdx.x, j = threadIdx.x;  // 192
    __shared__ float hs[DK];
    __shared__ float gh_s[192];
    if (j < DK) hs[j] = 0.f;
    __syncthreads();
    float bh = b_hh[j];
    for (int t = 0; t < 31; t++) {
        float gh = bh;
        #pragma unroll 8
        for (int k2 = 0; k2 < DK; k2++) gh += hs[k2]*d_WhhT[k2*192 + j];
        gh_s[j] = gh;
        __syncthreads();
        float hn = 0.f;
        if (j < DK) {
            const float* gi = d_gi + ((size_t)b*31 + t)*192;
            float r = 1.f/(1.f + __expf(-(gi[j] + gh_s[j])));
            float z = 1.f/(1.f + __expf(-(gi[64 + j] + gh_s[64 + j])));
            float n = tanhf(gi[128 + j] + r*gh_s[128 + j]);
            hn = (1.f - z)*n + z*hs[j];
        }
        __syncthreads();
        if (j < DK) hs[j] = hn;
        __syncthreads();
    }
    if (j < DK) d_res[b*DK + j] = hs[j];
}

// ---------------- fused deta + out ----------------
__global__ void __launch_bounds__(512) detaout_kernel(const float* __restrict__ bv,
                               const float* __restrict__ x_pre, const float* __restrict__ bO,
                               float* __restrict__ out) {
    int b = blockIdx.x, t = threadIdx.x;  // 512
    __shared__ float xb[8][DM];
    __shared__ float dd[DM];
    for (int i = t; i < 8*DM; i += 512)
        xb[i >> 9][i & 511] = d_xbar[(size_t)(b*HDIM + (i >> 9))*DM + (i & 511)];
    __syncthreads();
    int h = t >> 6, c = t & 63;
    const float* wt = d_WvMT + (size_t)h*DM*DK;
    float acc = 0.f;
    #pragma unroll 8
    for (int d = 0; d < DM; d++) acc += xb[h][d]*wt[d*DK + c];
    float al = d_alast[b*HDIM + h];
    dd[t] = acc + bv[h*DK + c]*(1.f - al) + al*d_res[b*DK + c];
    __syncthreads();
    float o = bO[t];
    #pragma unroll 8
    for (int i = 0; i < DM; i++) o += dd[i]*d_WOMT[(size_t)i*DM + t];
    out[(size_t)b*DM + t] = x_pre[(size_t)b*DM + t] + o;
}

extern "C" void kernel_launch(void* const* d_in, const int* in_sizes, int n_in,
                              void* d_out, int out_size) {
    const float* memory = (const float*)d_in[0];
    const float* x_pre  = (const float*)d_in[1];
    const float* aux    = (const float*)d_in[2];
    const float* pos    = (const float*)d_in[3];
    const float* Wq  = (const float*)d_in[4];
    const float* bq  = (const float*)d_in[5];
    const float* Wk  = (const float*)d_in[6];
    const float* bk  = (const float*)d_in[7];
    const float* Wv  = (const float*)d_in[8];
    const float* bv  = (const float*)d_in[9];
    const float* Wqa = (const float*)d_in[10];
    const float* bqa = (const float*)d_in[11];
    const float* Wka = (const float*)d_in[12];
    const float* bka = (const float*)d_in[13];
    const float* Wqp = (const float*)d_in[14];
    const float* bqp = (const float*)d_in[15];
    const float* Wkp = (const float*)d_in[16];
    const float* bkp = (const float*)d_in[17];
    const float* W_ih = (const float*)d_in[18];
    const float* W_hh = (const float*)d_in[19];
    const float* b_ih = (const float*)d_in[20];
    const float* b_hh = (const float*)d_in[21];
    const float* WO = (const float*)d_in[22];
    const float* bO = (const float*)d_in[23];
    const float* w   = (const float*)d_in[24];
    const float* w_a = (const float*)d_in[25];
    const float* w_p = (const float*)d_in[26];
    const int* G = (const int*)d_in[27];
    float* out = (float*)d_out;

    int S  = in_sizes[2] / (BDIM*DA);   // 6144
    int Wn = S - MDIM + 1;              // 6113

    __nv_bfloat16 *Xbf_p, *Abf_p, *Pbf_p, *WkMbf_p, *Wkabf_p, *Wkpbf_p;
    cudaGetSymbolAddress((void**)&Xbf_p, d_Xbf);
    cudaGetSymbolAddress((void**)&Abf_p, d_Abf);
    cudaGetSymbolAddress((void**)&Pbf_p, d_Pbf);
    cudaGetSymbolAddress((void**)&WkMbf_p, d_WkMbf);
    cudaGetSymbolAddress((void**)&Wkabf_p, d_Wkabf);
    cudaGetSymbolAddress((void**)&Wkpbf_p, d_Wkpbf);

    const int smem_k = (128 + 128)*68*4;   // 69632
    const int smem_a = (128 + 64)*68*4;    // 52224
    const int smem_p = (128 + 32)*68*4;    // 43520
    cudaFuncSetAttribute(proj_mma_kernel<DM, 128, 0>,
                         cudaFuncAttributeMaxDynamicSharedMemorySize, smem_k);
    cudaFuncSetAttribute(proj_mma_kernel<DA, 64, 1>,
                         cudaFuncAttributeMaxDynamicSharedMemorySize, smem_a);
    cudaFuncSetAttribute(proj_mma_kernel<DP, 32, 2>,
                         cudaFuncAttributeMaxDynamicSharedMemorySize, smem_p);

    // persistent side streams + events (created once; never destroyed — a
    // destroy during graph capture would invalidate the capture)
    static cudaStream_t s1 = [](){ cudaStream_t s; cudaStreamCreateWithFlags(&s, cudaStreamNonBlocking); return s; }();
    static cudaStream_t s2 = [](){ cudaStream_t s; cudaStreamCreateWithFlags(&s, cudaStreamNonBlocking); return s; }();
    static cudaStream_t s3 = [](){ cudaStream_t s; cudaStreamCreateWithFlags(&s, cudaStreamNonBlocking); return s; }();
    static cudaEvent_t e1  = [](){ cudaEvent_t e; cudaEventCreateWithFlags(&e, cudaEventDisableTiming); return e; }();
    static cudaEvent_t eqv = [](){ cudaEvent_t e; cudaEventCreateWithFlags(&e, cudaEventDisableTiming); return e; }();
    static cudaEvent_t e2a = [](){ cudaEvent_t e; cudaEventCreateWithFlags(&e, cudaEventDisableTiming); return e; }();
    static cudaEvent_t e2b = [](){ cudaEvent_t e; cudaEventCreateWithFlags(&e, cudaEventDisableTiming); return e; }();
    static cudaEvent_t e2c = [](){ cudaEvent_t e; cudaEventCreateWithFlags(&e, cudaEventDisableTiming); return e; }();

    // ---- s0 (capture stream): prerequisites ----
    convert_kernel<<<dim3(512, BDIM), 256>>>(memory, x_pre, aux, pos, S);
    mask_kernel<<<1024, 256>>>(Wq, Wk, Wv, WO, W_ih, W_hh, Wka, Wkp, G);
    qaqp_kernel<<<BDIM*HDIM, 64>>>(aux, Wqa, bqa, pos, Wqp, bqp, S);
    cudaEventRecord(e1, 0);

    // ---- s3: qv -> gi -> gru ----
    cudaStreamWaitEvent(s3, e1, 0);
    qv_kernel<<<BDIM*HDIM*8, 256, 0, s3>>>(memory, x_pre, bq, S);
    cudaEventRecord(eqv, s3);
    gi_kernel<<<dim3(31, BDIM), 192, 0, s3>>>(memory, b_ih, S);
    gru_kernel<<<BDIM, 192, 0, s3>>>(b_hh);
    cudaEventRecord(e2c, s3);

    // ---- s1: dota ----
    cudaStreamWaitEvent(s1, e1, 0);
    proj_mma_kernel<DA, 64, 1><<<dim3(S/128, HDIM/2, BDIM), 256, smem_a, s1>>>(Abf_p, Wkabf_p, bka, S, Wn);
    cudaEventRecord(e2a, s1);

    // ---- s2: dotp ----
    cudaStreamWaitEvent(s2, e1, 0);
    proj_mma_kernel<DP, 32, 2><<<dim3(S/128, HDIM/2, BDIM), 256, smem_p, s2>>>(Pbf_p, Wkpbf_p, bkp, S, Wn);
    cudaEventRecord(e2b, s2);

    // ---- s0: kproj -> band -> softmax -> xbar -> detaout ----
    proj_mma_kernel<DM, 128, 0><<<dim3(S/128, HDIM/2, BDIM), 256, smem_k>>>(Xbf_p, WkMbf_p, bk, S, Wn);
    cudaStreamWaitEvent(0, eqv, 0);
    band_mma_kernel<<<dim3((Wn + 63)/64, HDIM, BDIM), 128>>>(S, Wn);
    cudaStreamWaitEvent(0, e2a, 0);
    cudaStreamWaitEvent(0, e2b, 0);
    softmax_kernel<<<BDIM*HDIM, 256>>>(w, w_a, w_p, S, Wn);
    xbar_kernel<<<dim3((Wn - 1 + 63)/64, BDIM), 256>>>(S, Wn);
    cudaStreamWaitEvent(0, e2c, 0);
    detaout_kernel<<<BDIM, 512>>>(bv, x_pre, bO, out);
}